// round 13
// baseline (speedup 1.0000x reference)
#include <cuda_runtime.h>
#include <math.h>
#include <stdint.h>

#define BB 4
#define CC 64
#define C3 192
#define TT 10
#define HH 64
#define WW 64
#define HW 4096
#define THW 40960
#define HEADS 4
#define CPH 16
#define NN 160
#define DD 4096
#define BH (BB*HEADS)
#define KSPL 8
#define KCH (DD/KSPL)   // 512

// ---------------- scratch (device globals) ---------------------------------
__device__ float g_qkv0[(size_t)BB * C3 * THW];
__device__ float g_qkv1[(size_t)BB * C3 * THW];
__device__ float g_Spart[(size_t)KSPL * BH * NN * NN];
__device__ float g_S[(size_t)BH * NN * NN];
__device__ float g_nq2[BH * NN];     // sum-of-squares accumulators
__device__ float g_nk2[BH * NN];
__device__ float g_O[(size_t)BB * CC * THW];

// ---------------- packed f32x2 helpers --------------------------------------
__device__ __forceinline__ void ffma2(unsigned long long& d,
                                      unsigned long long a, unsigned long long b) {
    asm("fma.rn.f32x2 %0, %1, %2, %0;" : "+l"(d) : "l"(a), "l"(b));
}
__device__ __forceinline__ unsigned long long dup2(float x) {
    unsigned long long r;
    asm("mov.b64 %0, {%1, %1};" : "=l"(r) : "f"(x));
    return r;
}
__device__ __forceinline__ float2 unpk(unsigned long long v) {
    float2 r;
    asm("mov.b64 {%0, %1}, %2;" : "=f"(r.x), "=f"(r.y) : "l"(v));
    return r;
}
__device__ __forceinline__ unsigned long long lds64(const float* p) {
    return *(const unsigned long long*)p;
}
__device__ __forceinline__ uint32_t smem_u32(const void* p) {
    uint32_t a;
    asm("{ .reg .u64 t; cvta.to.shared.u64 t, %1; cvt.u32.u64 %0, t; }" : "=r"(a) : "l"(p));
    return a;
}
__device__ __forceinline__ void cpasync16(uint32_t dst, const void* src) {
    asm volatile("cp.async.cg.shared.global [%0], [%1], 16;" :: "r"(dst), "l"(src));
}
#define CP_COMMIT() asm volatile("cp.async.commit_group;" ::: "memory")
#define CP_WAIT1()  asm volatile("cp.async.wait_group 1;" ::: "memory")
#define CP_WAIT0()  asm volatile("cp.async.wait_group 0;" ::: "memory")

// ---------------- K1 / K7: projection GEMM (FFMA2, multi-CTA/SM) ------------
__global__ __launch_bounds__(128) void gemm_proj2(
    const float* __restrict__ W, const float* __restrict__ X, float* __restrict__ Y,
    long xbstride, long ybstride, int zero_norms)
{
    __shared__ __align__(16) float As2[32][132];
    __shared__ __align__(16) float Bs[32][132];
    const int b  = blockIdx.z;
    const int m0 = blockIdx.y * 64;
    const int p0 = blockIdx.x * 128;
    const float* Xb = X + (size_t)b * xbstride;
    float*       Yb = Y + (size_t)b * ybstride;
    const int tid = threadIdx.x;
    const int tm = tid >> 4, tn = tid & 15;

    if (zero_norms && blockIdx.x == 0 && blockIdx.y == 0 && blockIdx.z == 0) {
        for (int i = tid; i < BH * NN; i += 128) { g_nq2[i] = 0.f; g_nk2[i] = 0.f; }
    }

    unsigned long long acc[8][4];
    #pragma unroll
    for (int i = 0; i < 8; i++)
        #pragma unroll
        for (int j = 0; j < 4; j++) acc[i][j] = 0ull;

    for (int kb = 0; kb < 64; kb += 32) {
        #pragma unroll
        for (int j = 0; j < 4; j++) {
            int idx = tid + j * 128;
            int row = idx >> 3;
            int kc  = (idx & 7) * 4;
            float4 w4 = *(const float4*)&W[(size_t)(m0 + row) * 64 + kb + kc];
            *(unsigned long long*)&As2[kc + 0][2 * row] = dup2(w4.x);
            *(unsigned long long*)&As2[kc + 1][2 * row] = dup2(w4.y);
            *(unsigned long long*)&As2[kc + 2][2 * row] = dup2(w4.z);
            *(unsigned long long*)&As2[kc + 3][2 * row] = dup2(w4.w);
        }
        #pragma unroll
        for (int j = 0; j < 8; j++) {
            int idx = tid + j * 128;
            int row = idx >> 5;
            int col = (idx & 31) * 4;
            *(float4*)&Bs[row][col] = *(const float4*)&Xb[(size_t)(kb + row) * THW + p0 + col];
        }
        __syncthreads();
        #pragma unroll 4
        for (int k = 0; k < 32; k++) {
            unsigned long long a[8], bp[4];
            #pragma unroll
            for (int mi = 0; mi < 8; mi++) a[mi] = lds64(&As2[k][2 * (tm * 8 + mi)]);
            #pragma unroll
            for (int u = 0; u < 4; u++)    bp[u] = lds64(&Bs[k][2 * tn + 32 * u]);
            #pragma unroll
            for (int mi = 0; mi < 8; mi++)
                #pragma unroll
                for (int u = 0; u < 4; u++) ffma2(acc[mi][u], a[mi], bp[u]);
        }
        __syncthreads();
    }
    #pragma unroll
    for (int mi = 0; mi < 8; mi++) {
        size_t base = (size_t)(m0 + tm * 8 + mi) * THW + p0 + 2 * tn;
        #pragma unroll
        for (int u = 0; u < 4; u++)
            *(float2*)&Yb[base + 32 * u] = unpk(acc[mi][u]);
    }
}

// ---------------- K2: depthwise 3x3 + temporal mix, 16x64 strips -------------
// channel range [c0, c0+cn); grid (4 strips, BB*cn)
__global__ __launch_bounds__(256) void dwconv_tmix3(
    const float* __restrict__ wdw, const float* __restrict__ wt,
    const float* __restrict__ bt, int c0, int cn)
{
    __shared__ __align__(16) float tile[TT][18][68];
    __shared__ float wts[TT * TT + TT];
    const int by = blockIdx.y;
    const int b  = by / cn;
    const int c  = c0 + by % cn;
    const int bc = b * C3 + c;
    const int h0 = blockIdx.x * 16;
    const float* src = g_qkv0 + (size_t)bc * THW;
    float*       dst = g_qkv1 + (size_t)bc * THW;
    const int tid = threadIdx.x;

    if (tid < TT * TT + TT)
        wts[tid] = (tid < TT * TT) ? wt[tid] : bt[tid - TT * TT];

    for (int idx = tid; idx < TT * 18 * 66; idx += 256) {
        int t = idx / (18 * 66);
        int rem = idx % (18 * 66);
        int y = rem / 66, x = rem % 66;
        int gh = h0 + y - 1, gw = x - 1;
        float v = 0.f;
        if (gh >= 0 && gh < HH && gw >= 0 && gw < WW)
            v = src[(size_t)t * HW + gh * WW + gw];
        tile[t][y][x] = v;
    }
    __syncthreads();

    float wd[9];
    #pragma unroll
    for (int i = 0; i < 9; i++) wd[i] = wdw[c * 9 + i];

    const int y  = tid >> 4;
    const int x0 = (tid & 15) * 4;

    float cv[4][TT];
    #pragma unroll
    for (int xx = 0; xx < 4; xx++)
        #pragma unroll
        for (int t = 0; t < TT; t++) cv[xx][t] = 0.f;

    #pragma unroll
    for (int t = 0; t < TT; t++) {
        #pragma unroll
        for (int kh = 0; kh < 3; kh++) {
            const float* row = &tile[t][y + kh][x0];
            float4 q = *(const float4*)row;
            float2 r2 = *(const float2*)(row + 4);
            float w0 = wd[kh * 3], w1 = wd[kh * 3 + 1], w2 = wd[kh * 3 + 2];
            cv[0][t] += w0 * q.x + w1 * q.y  + w2 * q.z;
            cv[1][t] += w0 * q.y + w1 * q.z  + w2 * q.w;
            cv[2][t] += w0 * q.z + w1 * q.w  + w2 * r2.x;
            cv[3][t] += w0 * q.w + w1 * r2.x + w2 * r2.y;
        }
    }

    const int hw = (h0 + y) * WW + x0;
    #pragma unroll
    for (int s = 0; s < TT; s++) {
        float bs = wts[TT * TT + s];
        float4 o = make_float4(bs, bs, bs, bs);
        #pragma unroll
        for (int t = 0; t < TT; t++) {
            float w = wts[s * TT + t];
            o.x += w * cv[0][t];
            o.y += w * cv[1][t];
            o.z += w * cv[2][t];
            o.w += w * cv[3][t];
        }
        *(float4*)&dst[(size_t)s * HW + hw] = o;
    }
}

// ---------------- K3b: S partials = Q K^T + fused sum-of-squares ------------
#define QAS 330                        // dup-A row stride (floats)
#define QBS 166                        // K row stride (floats)
#define QK_STG (32 * QAS + 32 * QBS)   // one stage, floats
#define QK_NORM_OFF (2 * QK_STG)       // 320-float norm scratch after stages

__global__ __launch_bounds__(512, 1) void qk_gemm8()
{
    extern __shared__ __align__(16) float sm[];
    float* snorm = sm + QK_NORM_OFF;    // [320]: 0..159 Q rows, 160..319 K rows
    const int bh = blockIdx.x;
    const int ks = blockIdx.y;
    const int b = bh >> 2, h = bh & 3;
    const float* Q  = g_qkv1 + ((size_t)b * C3 + h * CPH) * THW + (size_t)ks * KCH;
    const float* Kp = Q + (size_t)CC * THW;
    const int tid = threadIdx.x;
    const int tm = tid >> 4;
    const int tn = tid & 15;

    int lisK[5], lrow[5], lseg[5];
    #pragma unroll
    for (int j = 0; j < 5; j++) {
        int idx = tid + j * 512;
        lisK[j] = idx >= 1280;
        int l = idx - lisK[j] * 1280;
        lrow[j] = l >> 3;
        lseg[j] = (l & 7) * 4;
    }

    if (tid < 320) snorm[tid] = 0.f;

    unsigned long long acc[5][5];
    #pragma unroll
    for (int i = 0; i < 5; i++)
        #pragma unroll
        for (int j = 0; j < 5; j++) acc[i][j] = 0ull;

    float ss[5] = {0.f, 0.f, 0.f, 0.f, 0.f};   // per-segment sum of squares

    float4 r[5];
    auto gload = [&](int c) {
        const int kb = c * 32;
        #pragma unroll
        for (int j = 0; j < 5; j++)
            r[j] = *(const float4*)((lisK[j] ? Kp : Q) + (size_t)lrow[j] * DD + kb + lseg[j]);
    };
    auto sstore = [&](int s) {
        float* Qs2 = sm + s * QK_STG;
        float* Ksh = Qs2 + 32 * QAS;
        #pragma unroll
        for (int j = 0; j < 5; j++) {
            ss[j] += r[j].x * r[j].x + r[j].y * r[j].y
                   + r[j].z * r[j].z + r[j].w * r[j].w;
            if (lisK[j]) {
                Ksh[(lseg[j] + 0) * QBS + lrow[j]] = r[j].x;
                Ksh[(lseg[j] + 1) * QBS + lrow[j]] = r[j].y;
                Ksh[(lseg[j] + 2) * QBS + lrow[j]] = r[j].z;
                Ksh[(lseg[j] + 3) * QBS + lrow[j]] = r[j].w;
            } else {
                *(unsigned long long*)&Qs2[(lseg[j] + 0) * QAS + 2 * lrow[j]] = dup2(r[j].x);
                *(unsigned long long*)&Qs2[(lseg[j] + 1) * QAS + 2 * lrow[j]] = dup2(r[j].y);
                *(unsigned long long*)&Qs2[(lseg[j] + 2) * QAS + 2 * lrow[j]] = dup2(r[j].z);
                *(unsigned long long*)&Qs2[(lseg[j] + 3) * QAS + 2 * lrow[j]] = dup2(r[j].w);
            }
        }
    };

    gload(0);
    sstore(0);
    __syncthreads();

    for (int c = 0; c < 16; c++) {
        if (c < 15) gload(c + 1);
        const float* Qs2 = sm + (c & 1) * QK_STG;
        const float* Ksh = Qs2 + 32 * QAS;
        #pragma unroll 4
        for (int k = 0; k < 32; k++) {
            unsigned long long a[5], bp[5];
            #pragma unroll
            for (int g = 0; g < 5; g++) a[g]  = lds64(&Qs2[k * QAS + 10 * tm + 2 * g]);
            #pragma unroll
            for (int u = 0; u < 5; u++) bp[u] = lds64(&Ksh[k * QBS + 2 * tn + 32 * u]);
            #pragma unroll
            for (int g = 0; g < 5; g++)
                #pragma unroll
                for (int u = 0; u < 5; u++) ffma2(acc[g][u], a[g], bp[u]);
        }
        if (c < 15) sstore((c + 1) & 1);
        __syncthreads();
    }

    // norm epilogue: smem-reduce per row, then one atomic per row to global
    #pragma unroll
    for (int j = 0; j < 5; j++)
        atomicAdd(&snorm[lisK[j] * 160 + lrow[j]], ss[j]);

    float* Sp = g_Spart + ((size_t)ks * BH + bh) * NN * NN;
    #pragma unroll
    for (int g = 0; g < 5; g++) {
        int gi = tm * 5 + g;
        #pragma unroll
        for (int u = 0; u < 5; u++)
            *(float2*)&Sp[(size_t)gi * NN + 2 * tn + 32 * u] = unpk(acc[g][u]);
    }

    __syncthreads();
    if (tid < 320) {
        float* dst = (tid < 160) ? &g_nq2[bh * NN + tid]
                                 : &g_nk2[bh * NN + tid - 160];
        atomicAdd(dst, snorm[tid]);
    }
}

// ---------------- K3c: reduce split-K + norms + scale + softmax -------------
__global__ __launch_bounds__(256) void softmax2(const float* __restrict__ temp)
{
    const int warp = (blockIdx.x * 256 + threadIdx.x) >> 5;
    const int lane = threadIdx.x & 31;
    if (warp >= BH * NN) return;
    const int bh = warp / NN, i = warp % NN;
    const int h = bh & 3;
    const float invq = 1.f / fmaxf(sqrtf(g_nq2[bh * NN + i]), 1e-12f);
    const float scale_i = invq * temp[h];
    float vals[5];
    float mx = -1e30f;
    #pragma unroll
    for (int j5 = 0; j5 < 5; j5++) {
        int j = lane + j5 * 32;
        float s = 0.f;
        #pragma unroll
        for (int ks = 0; ks < KSPL; ks++)
            s += g_Spart[(((size_t)ks * BH + bh) * NN + i) * NN + j];
        float invk = 1.f / fmaxf(sqrtf(g_nk2[bh * NN + j]), 1e-12f);
        vals[j5] = s * scale_i * invk;
        mx = fmaxf(mx, vals[j5]);
    }
    #pragma unroll
    for (int off = 16; off; off >>= 1) mx = fmaxf(mx, __shfl_xor_sync(0xffffffffu, mx, off));
    float s = 0.f;
    #pragma unroll
    for (int j5 = 0; j5 < 5; j5++) { vals[j5] = __expf(vals[j5] - mx); s += vals[j5]; }
    #pragma unroll
    for (int off = 16; off; off >>= 1) s += __shfl_xor_sync(0xffffffffu, s, off);
    const float invs = 1.f / s;
    float* row = g_S + (size_t)bh * NN * NN + (size_t)i * NN;
    #pragma unroll
    for (int j5 = 0; j5 < 5; j5++) row[lane + j5 * 32] = vals[j5] * invs;
}

// ---------------- K3d: O = P V ----------------------------------------------
#define PS 36                          // P row stride (floats)
#define VS 264                         // V row stride (floats)
#define PV_STAGE (80 * PS + 32 * VS)   // floats

__global__ __launch_bounds__(256, 2) void pv_gemm5()
{
    extern __shared__ __align__(16) float sm[];
    const uint32_t sbase = smem_u32(sm);
    const int bh = blockIdx.z;
    const int b = bh >> 2, h = bh & 3;
    const int i0 = blockIdx.y * 80;
    const int d0 = blockIdx.x * 256;
    const float* P = g_S + (size_t)bh * NN * NN;
    const float* V = g_qkv1 + ((size_t)b * C3 + 2 * CC + h * CPH) * THW;
    float*       O = g_O   + ((size_t)b * CC + h * CPH) * THW;
    const int tid = threadIdx.x;
    const int tm = tid >> 4, tn = tid & 15;

    auto copy_chunk = [&](int c, int s) {
        const int kb = c * 32;
        #pragma unroll
        for (int j = 0; j < 3; j++) {
            int idx = tid + j * 256;
            if (idx < 640) {
                int row = idx >> 3, seg = idx & 7;
                cpasync16(sbase + (uint32_t)(s * PV_STAGE + row * PS + seg * 4) * 4u,
                          P + (size_t)(i0 + row) * NN + kb + seg * 4);
            }
        }
        #pragma unroll
        for (int j = 0; j < 8; j++) {
            int idx = tid + j * 256;
            int row = idx >> 6, col = (idx & 63) * 4;
            cpasync16(sbase + (uint32_t)(s * PV_STAGE + 80 * PS + row * VS + col) * 4u,
                      V + (size_t)(kb + row) * DD + d0 + col);
        }
        CP_COMMIT();
    };

    unsigned long long acc[5][8];
    #pragma unroll
    for (int i = 0; i < 5; i++)
        #pragma unroll
        for (int j = 0; j < 8; j++) acc[i][j] = 0ull;

    copy_chunk(0, 0);
    copy_chunk(1, 1);

    for (int c = 0; c < 5; c++) {
        if (c < 4) { CP_WAIT1(); } else { CP_WAIT0(); }
        __syncthreads();
        const float* Ps = sm + (c & 1) * PV_STAGE;
        const float* Vs = Ps + 80 * PS;
        #pragma unroll 4
        for (int k = 0; k < 32; k++) {
            unsigned long long bp[8];
            #pragma unroll
            for (int u = 0; u < 8; u++)
                bp[u] = lds64(&Vs[k * VS + 2 * tn + 32 * u]);
            #pragma unroll
            for (int v = 0; v < 5; v++) {
                unsigned long long a = dup2(Ps[(tm * 5 + v) * PS + k]);
                #pragma unroll
                for (int u = 0; u < 8; u++) ffma2(acc[v][u], a, bp[u]);
            }
        }
        __syncthreads();
        if (c < 3) copy_chunk(c + 2, c & 1);
    }

    #pragma unroll
    for (int v = 0; v < 5; v++) {
        size_t base = (size_t)(i0 + tm * 5 + v) * DD + d0 + 2 * tn;
        #pragma unroll
        for (int u = 0; u < 8; u++)
            *(float2*)&O[base + 32 * u] = unpk(acc[v][u]);
    }
}

// ---------------- host launcher --------------------------------------------
extern "C" void kernel_launch(void* const* d_in, const int* in_sizes, int n_in,
                              void* d_out, int out_size)
{
    const float* x      = (const float*)d_in[0];
    const float* w_qkv  = (const float*)d_in[1];
    const float* w_dw   = (const float*)d_in[2];
    const float* w_t    = (const float*)d_in[3];
    const float* b_t    = (const float*)d_in[4];
    const float* temp   = (const float*)d_in[5];
    const float* w_out  = (const float*)d_in[6];
    float* out = (float*)d_out;

    float *qkv0, *obuf;
    cudaGetSymbolAddress((void**)&qkv0, g_qkv0);
    cudaGetSymbolAddress((void**)&obuf, g_O);

    const int qk_smem = (2 * QK_STG + 320) * 4;   // 128256 B
    const int pv_smem = 2 * PV_STAGE * 4;         // 90624 B
    cudaFuncSetAttribute(qk_gemm8, cudaFuncAttributeMaxDynamicSharedMemorySize, qk_smem);
    cudaFuncSetAttribute(pv_gemm5, cudaFuncAttributeMaxDynamicSharedMemorySize, pv_smem);

    cudaStream_t s2;
    cudaEvent_t e1, e2;
    cudaStreamCreateWithFlags(&s2, cudaStreamNonBlocking);
    cudaEventCreateWithFlags(&e1, cudaEventDisableTiming);
    cudaEventCreateWithFlags(&e2, cudaEventDisableTiming);

    // K1: qkv projection (also zeroes norm accumulators)
    gemm_proj2<<<dim3(THW / 128, C3 / 64, BB), 128>>>(
        w_qkv, x, qkv0, (long)CC * THW, (long)C3 * THW, 1);

    // K2a: depthwise + temporal mix for q,k channels (critical path)
    dwconv_tmix3<<<dim3(4, BB * 128), 256>>>(w_dw, w_t, b_t, 0, 128);
    cudaEventRecord(e1, 0);

    // side stream: v channels only, overlapped with qk + softmax
    cudaStreamWaitEvent(s2, e1, 0);
    dwconv_tmix3<<<dim3(4, BB * 64), 256, 0, s2>>>(w_dw, w_t, b_t, 128, 64);
    cudaEventRecord(e2, s2);

    // K3b: split-K scores + fused sum-of-squares
    qk_gemm8<<<dim3(BH, KSPL), 512, qk_smem>>>();

    // K3c: reduce + norms + scale + softmax
    softmax2<<<(BH * NN) / 8, 256>>>(temp);

    // join: pv needs v channels
    cudaStreamWaitEvent(0, e2, 0);

    // K3d: O = P V
    pv_gemm5<<<dim3(DD / 256, NN / 80, BH), 256, pv_smem>>>();

    // K7: final projection -> d_out
    gemm_proj2<<<dim3(THW / 128, 1, BB), 128>>>(
        w_out, obuf, out, (long)CC * THW, (long)CC * THW, 0);
}

// round 14
// speedup vs baseline: 1.0064x; 1.0064x over previous
#include <cuda_runtime.h>
#include <math.h>
#include <stdint.h>

#define BB 4
#define CC 64
#define C3 192
#define TT 10
#define HH 64
#define WW 64
#define HW 4096
#define THW 40960
#define HEADS 4
#define CPH 16
#define NN 160
#define DD 4096
#define BH (BB*HEADS)
#define KSPL 8
#define KCH (DD/KSPL)   // 512

// ---------------- scratch (device globals) ---------------------------------
__device__ float g_qkv0[(size_t)BB * C3 * THW];
__device__ float g_qkv1[(size_t)BB * C3 * THW];
__device__ float g_Spart[(size_t)KSPL * BH * NN * NN];
__device__ float g_S[(size_t)BH * NN * NN];
__device__ float g_invq[BH * NN];
__device__ float g_invk[BH * NN];
__device__ float g_O[(size_t)BB * CC * THW];

// ---------------- packed f32x2 helpers --------------------------------------
__device__ __forceinline__ void ffma2(unsigned long long& d,
                                      unsigned long long a, unsigned long long b) {
    asm("fma.rn.f32x2 %0, %1, %2, %0;" : "+l"(d) : "l"(a), "l"(b));
}
__device__ __forceinline__ unsigned long long dup2(float x) {
    unsigned long long r;
    asm("mov.b64 %0, {%1, %1};" : "=l"(r) : "f"(x));
    return r;
}
__device__ __forceinline__ float2 unpk(unsigned long long v) {
    float2 r;
    asm("mov.b64 {%0, %1}, %2;" : "=f"(r.x), "=f"(r.y) : "l"(v));
    return r;
}
__device__ __forceinline__ unsigned long long lds64(const float* p) {
    return *(const unsigned long long*)p;
}
__device__ __forceinline__ uint32_t smem_u32(const void* p) {
    uint32_t a;
    asm("{ .reg .u64 t; cvta.to.shared.u64 t, %1; cvt.u32.u64 %0, t; }" : "=r"(a) : "l"(p));
    return a;
}
__device__ __forceinline__ void cpasync16(uint32_t dst, const void* src) {
    asm volatile("cp.async.cg.shared.global [%0], [%1], 16;" :: "r"(dst), "l"(src));
}
#define CP_COMMIT() asm volatile("cp.async.commit_group;" ::: "memory")
#define CP_WAIT1()  asm volatile("cp.async.wait_group 1;" ::: "memory")
#define CP_WAIT0()  asm volatile("cp.async.wait_group 0;" ::: "memory")

// ---------------- K1 / K7: projection GEMM (FFMA2, multi-CTA/SM) ------------
// m0 = moff + blockIdx.y*64 lets the launcher split output channels.
__global__ __launch_bounds__(128) void gemm_proj2(
    const float* __restrict__ W, const float* __restrict__ X, float* __restrict__ Y,
    long xbstride, long ybstride, int moff)
{
    __shared__ __align__(16) float As2[32][132];
    __shared__ __align__(16) float Bs[32][132];
    const int b  = blockIdx.z;
    const int m0 = moff + blockIdx.y * 64;
    const int p0 = blockIdx.x * 128;
    const float* Xb = X + (size_t)b * xbstride;
    float*       Yb = Y + (size_t)b * ybstride;
    const int tid = threadIdx.x;
    const int tm = tid >> 4, tn = tid & 15;

    unsigned long long acc[8][4];
    #pragma unroll
    for (int i = 0; i < 8; i++)
        #pragma unroll
        for (int j = 0; j < 4; j++) acc[i][j] = 0ull;

    for (int kb = 0; kb < 64; kb += 32) {
        #pragma unroll
        for (int j = 0; j < 4; j++) {
            int idx = tid + j * 128;
            int row = idx >> 3;
            int kc  = (idx & 7) * 4;
            float4 w4 = *(const float4*)&W[(size_t)(m0 + row) * 64 + kb + kc];
            *(unsigned long long*)&As2[kc + 0][2 * row] = dup2(w4.x);
            *(unsigned long long*)&As2[kc + 1][2 * row] = dup2(w4.y);
            *(unsigned long long*)&As2[kc + 2][2 * row] = dup2(w4.z);
            *(unsigned long long*)&As2[kc + 3][2 * row] = dup2(w4.w);
        }
        #pragma unroll
        for (int j = 0; j < 8; j++) {
            int idx = tid + j * 128;
            int row = idx >> 5;
            int col = (idx & 31) * 4;
            *(float4*)&Bs[row][col] = *(const float4*)&Xb[(size_t)(kb + row) * THW + p0 + col];
        }
        __syncthreads();
        #pragma unroll 4
        for (int k = 0; k < 32; k++) {
            unsigned long long a[8], bp[4];
            #pragma unroll
            for (int mi = 0; mi < 8; mi++) a[mi] = lds64(&As2[k][2 * (tm * 8 + mi)]);
            #pragma unroll
            for (int u = 0; u < 4; u++)    bp[u] = lds64(&Bs[k][2 * tn + 32 * u]);
            #pragma unroll
            for (int mi = 0; mi < 8; mi++)
                #pragma unroll
                for (int u = 0; u < 4; u++) ffma2(acc[mi][u], a[mi], bp[u]);
        }
        __syncthreads();
    }
    #pragma unroll
    for (int mi = 0; mi < 8; mi++) {
        size_t base = (size_t)(m0 + tm * 8 + mi) * THW + p0 + 2 * tn;
        #pragma unroll
        for (int u = 0; u < 4; u++)
            *(float2*)&Yb[base + 32 * u] = unpk(acc[mi][u]);
    }
}

// ---------------- K2: depthwise 3x3 + temporal mix, 16x64 strips -------------
// channel range [c0, c0+cn); grid (4 strips, BB*cn)
__global__ __launch_bounds__(256) void dwconv_tmix3(
    const float* __restrict__ wdw, const float* __restrict__ wt,
    const float* __restrict__ bt, int c0, int cn)
{
    __shared__ __align__(16) float tile[TT][18][68];
    __shared__ float wts[TT * TT + TT];
    const int by = blockIdx.y;
    const int b  = by / cn;
    const int c  = c0 + by % cn;
    const int bc = b * C3 + c;
    const int h0 = blockIdx.x * 16;
    const float* src = g_qkv0 + (size_t)bc * THW;
    float*       dst = g_qkv1 + (size_t)bc * THW;
    const int tid = threadIdx.x;

    if (tid < TT * TT + TT)
        wts[tid] = (tid < TT * TT) ? wt[tid] : bt[tid - TT * TT];

    for (int idx = tid; idx < TT * 18 * 66; idx += 256) {
        int t = idx / (18 * 66);
        int rem = idx % (18 * 66);
        int y = rem / 66, x = rem % 66;
        int gh = h0 + y - 1, gw = x - 1;
        float v = 0.f;
        if (gh >= 0 && gh < HH && gw >= 0 && gw < WW)
            v = src[(size_t)t * HW + gh * WW + gw];
        tile[t][y][x] = v;
    }
    __syncthreads();

    float wd[9];
    #pragma unroll
    for (int i = 0; i < 9; i++) wd[i] = wdw[c * 9 + i];

    const int y  = tid >> 4;
    const int x0 = (tid & 15) * 4;

    float cv[4][TT];
    #pragma unroll
    for (int xx = 0; xx < 4; xx++)
        #pragma unroll
        for (int t = 0; t < TT; t++) cv[xx][t] = 0.f;

    #pragma unroll
    for (int t = 0; t < TT; t++) {
        #pragma unroll
        for (int kh = 0; kh < 3; kh++) {
            const float* row = &tile[t][y + kh][x0];
            float4 q = *(const float4*)row;
            float2 r2 = *(const float2*)(row + 4);
            float w0 = wd[kh * 3], w1 = wd[kh * 3 + 1], w2 = wd[kh * 3 + 2];
            cv[0][t] += w0 * q.x + w1 * q.y  + w2 * q.z;
            cv[1][t] += w0 * q.y + w1 * q.z  + w2 * q.w;
            cv[2][t] += w0 * q.z + w1 * q.w  + w2 * r2.x;
            cv[3][t] += w0 * q.w + w1 * r2.x + w2 * r2.y;
        }
    }

    const int hw = (h0 + y) * WW + x0;
    #pragma unroll
    for (int s = 0; s < TT; s++) {
        float bs = wts[TT * TT + s];
        float4 o = make_float4(bs, bs, bs, bs);
        #pragma unroll
        for (int t = 0; t < TT; t++) {
            float w = wts[s * TT + t];
            o.x += w * cv[0][t];
            o.y += w * cv[1][t];
            o.z += w * cv[2][t];
            o.w += w * cv[3][t];
        }
        *(float4*)&dst[(size_t)s * HW + hw] = o;
    }
}

// ---------------- K3a: L2 norms of q/k rows ---------------------------------
__global__ __launch_bounds__(256) void norms_kernel()
{
    const int warp = (blockIdx.x * 256 + threadIdx.x) >> 5;
    const int lane = threadIdx.x & 31;
    if (warp >= 2 * BH * NN) return;
    const int qk = warp / (BH * NN);
    const int r  = warp % (BH * NN);
    const int bh = r / NN, i = r % NN;
    const int b = bh / HEADS, h = bh % HEADS;
    const float* row = g_qkv1 + ((size_t)b * C3 + qk * CC + h * CPH) * THW + (size_t)i * DD;
    float s = 0.f;
    for (int d = lane * 4; d < DD; d += 128) {
        float4 v = *(const float4*)&row[d];
        s += v.x * v.x + v.y * v.y + v.z * v.z + v.w * v.w;
    }
    #pragma unroll
    for (int off = 16; off; off >>= 1) s += __shfl_xor_sync(0xffffffffu, s, off);
    if (lane == 0) {
        float inv = 1.f / fmaxf(sqrtf(s), 1e-12f);
        (qk ? g_invk : g_invq)[bh * NN + i] = inv;
    }
}

// ---------------- K3b: S partials = Q K^T -----------------------------------
#define QAS 330                        // dup-A row stride (floats)
#define QBS 166                        // K row stride (floats)
#define QK_STG (32 * QAS + 32 * QBS)   // one stage, floats

__global__ __launch_bounds__(512, 1) void qk_gemm7()
{
    extern __shared__ __align__(16) float sm[];
    const int bh = blockIdx.x;
    const int ks = blockIdx.y;
    const int b = bh >> 2, h = bh & 3;
    const float* Q  = g_qkv1 + ((size_t)b * C3 + h * CPH) * THW + (size_t)ks * KCH;
    const float* Kp = Q + (size_t)CC * THW;
    const int tid = threadIdx.x;
    const int tm = tid >> 4;
    const int tn = tid & 15;

    int lisK[5], lrow[5], lseg[5];
    #pragma unroll
    for (int j = 0; j < 5; j++) {
        int idx = tid + j * 512;
        lisK[j] = idx >= 1280;
        int l = idx - lisK[j] * 1280;
        lrow[j] = l >> 3;
        lseg[j] = (l & 7) * 4;
    }

    unsigned long long acc[5][5];
    #pragma unroll
    for (int i = 0; i < 5; i++)
        #pragma unroll
        for (int j = 0; j < 5; j++) acc[i][j] = 0ull;

    float4 r[5];
    auto gload = [&](int c) {
        const int kb = c * 32;
        #pragma unroll
        for (int j = 0; j < 5; j++)
            r[j] = *(const float4*)((lisK[j] ? Kp : Q) + (size_t)lrow[j] * DD + kb + lseg[j]);
    };
    auto sstore = [&](int s) {
        float* Qs2 = sm + s * QK_STG;
        float* Ksh = Qs2 + 32 * QAS;
        #pragma unroll
        for (int j = 0; j < 5; j++) {
            if (lisK[j]) {
                Ksh[(lseg[j] + 0) * QBS + lrow[j]] = r[j].x;
                Ksh[(lseg[j] + 1) * QBS + lrow[j]] = r[j].y;
                Ksh[(lseg[j] + 2) * QBS + lrow[j]] = r[j].z;
                Ksh[(lseg[j] + 3) * QBS + lrow[j]] = r[j].w;
            } else {
                *(unsigned long long*)&Qs2[(lseg[j] + 0) * QAS + 2 * lrow[j]] = dup2(r[j].x);
                *(unsigned long long*)&Qs2[(lseg[j] + 1) * QAS + 2 * lrow[j]] = dup2(r[j].y);
                *(unsigned long long*)&Qs2[(lseg[j] + 2) * QAS + 2 * lrow[j]] = dup2(r[j].z);
                *(unsigned long long*)&Qs2[(lseg[j] + 3) * QAS + 2 * lrow[j]] = dup2(r[j].w);
            }
        }
    };

    gload(0);
    sstore(0);
    __syncthreads();

    for (int c = 0; c < 16; c++) {
        if (c < 15) gload(c + 1);
        const float* Qs2 = sm + (c & 1) * QK_STG;
        const float* Ksh = Qs2 + 32 * QAS;
        #pragma unroll 4
        for (int k = 0; k < 32; k++) {
            unsigned long long a[5], bp[5];
            #pragma unroll
            for (int g = 0; g < 5; g++) a[g]  = lds64(&Qs2[k * QAS + 10 * tm + 2 * g]);
            #pragma unroll
            for (int u = 0; u < 5; u++) bp[u] = lds64(&Ksh[k * QBS + 2 * tn + 32 * u]);
            #pragma unroll
            for (int g = 0; g < 5; g++)
                #pragma unroll
                for (int u = 0; u < 5; u++) ffma2(acc[g][u], a[g], bp[u]);
        }
        if (c < 15) sstore((c + 1) & 1);
        __syncthreads();
    }

    float* Sp = g_Spart + ((size_t)ks * BH + bh) * NN * NN;
    #pragma unroll
    for (int g = 0; g < 5; g++) {
        int gi = tm * 5 + g;
        #pragma unroll
        for (int u = 0; u < 5; u++)
            *(float2*)&Sp[(size_t)gi * NN + 2 * tn + 32 * u] = unpk(acc[g][u]);
    }
}

// ---------------- K3c: reduce split-K + scale + softmax ---------------------
__global__ __launch_bounds__(256) void softmax2(const float* __restrict__ temp)
{
    const int warp = (blockIdx.x * 256 + threadIdx.x) >> 5;
    const int lane = threadIdx.x & 31;
    if (warp >= BH * NN) return;
    const int bh = warp / NN, i = warp % NN;
    const int h = bh & 3;
    const float scale_i = g_invq[bh * NN + i] * temp[h];
    float vals[5];
    float mx = -1e30f;
    #pragma unroll
    for (int j5 = 0; j5 < 5; j5++) {
        int j = lane + j5 * 32;
        float s = 0.f;
        #pragma unroll
        for (int ks = 0; ks < KSPL; ks++)
            s += g_Spart[(((size_t)ks * BH + bh) * NN + i) * NN + j];
        vals[j5] = s * scale_i * g_invk[bh * NN + j];
        mx = fmaxf(mx, vals[j5]);
    }
    #pragma unroll
    for (int off = 16; off; off >>= 1) mx = fmaxf(mx, __shfl_xor_sync(0xffffffffu, mx, off));
    float s = 0.f;
    #pragma unroll
    for (int j5 = 0; j5 < 5; j5++) { vals[j5] = __expf(vals[j5] - mx); s += vals[j5]; }
    #pragma unroll
    for (int off = 16; off; off >>= 1) s += __shfl_xor_sync(0xffffffffu, s, off);
    const float invs = 1.f / s;
    float* row = g_S + (size_t)bh * NN * NN + (size_t)i * NN;
    #pragma unroll
    for (int j5 = 0; j5 < 5; j5++) row[lane + j5 * 32] = vals[j5] * invs;
}

// ---------------- K3d: O = P V ----------------------------------------------
#define PS 36                          // P row stride (floats)
#define VS 264                         // V row stride (floats)
#define PV_STAGE (80 * PS + 32 * VS)   // floats

__global__ __launch_bounds__(256, 2) void pv_gemm5()
{
    extern __shared__ __align__(16) float sm[];
    const uint32_t sbase = smem_u32(sm);
    const int bh = blockIdx.z;
    const int b = bh >> 2, h = bh & 3;
    const int i0 = blockIdx.y * 80;
    const int d0 = blockIdx.x * 256;
    const float* P = g_S + (size_t)bh * NN * NN;
    const float* V = g_qkv1 + ((size_t)b * C3 + 2 * CC + h * CPH) * THW;
    float*       O = g_O   + ((size_t)b * CC + h * CPH) * THW;
    const int tid = threadIdx.x;
    const int tm = tid >> 4, tn = tid & 15;

    auto copy_chunk = [&](int c, int s) {
        const int kb = c * 32;
        #pragma unroll
        for (int j = 0; j < 3; j++) {
            int idx = tid + j * 256;
            if (idx < 640) {
                int row = idx >> 3, seg = idx & 7;
                cpasync16(sbase + (uint32_t)(s * PV_STAGE + row * PS + seg * 4) * 4u,
                          P + (size_t)(i0 + row) * NN + kb + seg * 4);
            }
        }
        #pragma unroll
        for (int j = 0; j < 8; j++) {
            int idx = tid + j * 256;
            int row = idx >> 6, col = (idx & 63) * 4;
            cpasync16(sbase + (uint32_t)(s * PV_STAGE + 80 * PS + row * VS + col) * 4u,
                      V + (size_t)(kb + row) * DD + d0 + col);
        }
        CP_COMMIT();
    };

    unsigned long long acc[5][8];
    #pragma unroll
    for (int i = 0; i < 5; i++)
        #pragma unroll
        for (int j = 0; j < 8; j++) acc[i][j] = 0ull;

    copy_chunk(0, 0);
    copy_chunk(1, 1);

    for (int c = 0; c < 5; c++) {
        if (c < 4) { CP_WAIT1(); } else { CP_WAIT0(); }
        __syncthreads();
        const float* Ps = sm + (c & 1) * PV_STAGE;
        const float* Vs = Ps + 80 * PS;
        #pragma unroll 4
        for (int k = 0; k < 32; k++) {
            unsigned long long bp[8];
            #pragma unroll
            for (int u = 0; u < 8; u++)
                bp[u] = lds64(&Vs[k * VS + 2 * tn + 32 * u]);
            #pragma unroll
            for (int v = 0; v < 5; v++) {
                unsigned long long a = dup2(Ps[(tm * 5 + v) * PS + k]);
                #pragma unroll
                for (int u = 0; u < 8; u++) ffma2(acc[v][u], a, bp[u]);
            }
        }
        __syncthreads();
        if (c < 3) copy_chunk(c + 2, c & 1);
    }

    #pragma unroll
    for (int v = 0; v < 5; v++) {
        size_t base = (size_t)(i0 + tm * 5 + v) * DD + d0 + 2 * tn;
        #pragma unroll
        for (int u = 0; u < 8; u++)
            *(float2*)&O[base + 32 * u] = unpk(acc[v][u]);
    }
}

// ---------------- host launcher --------------------------------------------
extern "C" void kernel_launch(void* const* d_in, const int* in_sizes, int n_in,
                              void* d_out, int out_size)
{
    const float* x      = (const float*)d_in[0];
    const float* w_qkv  = (const float*)d_in[1];
    const float* w_dw   = (const float*)d_in[2];
    const float* w_t    = (const float*)d_in[3];
    const float* b_t    = (const float*)d_in[4];
    const float* temp   = (const float*)d_in[5];
    const float* w_out  = (const float*)d_in[6];
    float* out = (float*)d_out;

    float *qkv0, *obuf;
    cudaGetSymbolAddress((void**)&qkv0, g_qkv0);
    cudaGetSymbolAddress((void**)&obuf, g_O);

    const int qk_smem = 2 * QK_STG * 4;     // 126976 B
    const int pv_smem = 2 * PV_STAGE * 4;   // 90624 B
    cudaFuncSetAttribute(qk_gemm7, cudaFuncAttributeMaxDynamicSharedMemorySize, qk_smem);
    cudaFuncSetAttribute(pv_gemm5, cudaFuncAttributeMaxDynamicSharedMemorySize, pv_smem);

    cudaStream_t s2;
    cudaEvent_t e0, e1, e2;
    cudaStreamCreateWithFlags(&s2, cudaStreamNonBlocking);
    cudaEventCreateWithFlags(&e0, cudaEventDisableTiming);
    cudaEventCreateWithFlags(&e1, cudaEventDisableTiming);
    cudaEventCreateWithFlags(&e2, cudaEventDisableTiming);

    // K1-qk: projection for q,k channels only (critical path)
    gemm_proj2<<<dim3(THW / 128, 2, BB), 128>>>(
        w_qkv, x, qkv0, (long)CC * THW, (long)C3 * THW, 0);
    cudaEventRecord(e0, 0);

    // K2a: depthwise + temporal mix for q,k channels
    dwconv_tmix3<<<dim3(4, BB * 128), 256>>>(w_dw, w_t, b_t, 0, 128);
    cudaEventRecord(e1, 0);

    // side stream: K1-v (overlaps dwconv-qk), then dwconv-v + norms (overlap qk)
    cudaStreamWaitEvent(s2, e0, 0);
    gemm_proj2<<<dim3(THW / 128, 1, BB), 128, 0, s2>>>(
        w_qkv, x, qkv0, (long)CC * THW, (long)C3 * THW, 128);
    cudaStreamWaitEvent(s2, e1, 0);
    dwconv_tmix3<<<dim3(4, BB * 64), 256, 0, s2>>>(w_dw, w_t, b_t, 128, 64);
    norms_kernel<<<640, 256, 0, s2>>>();
    cudaEventRecord(e2, s2);

    // K3b: split-K scores (needs only q,k)
    qk_gemm7<<<dim3(BH, KSPL), 512, qk_smem>>>();

    // join: softmax needs norms; pv needs v
    cudaStreamWaitEvent(0, e2, 0);

    // K3c: reduce + scale + softmax
    softmax2<<<(BH * NN) / 8, 256>>>(temp);

    // K3d: O = P V
    pv_gemm5<<<dim3(DD / 256, NN / 80, BH), 256, pv_smem>>>();

    // K7: final projection -> d_out
    gemm_proj2<<<dim3(THW / 128, 1, BB), 128>>>(
        w_out, obuf, out, (long)CC * THW, (long)CC * THW, 0);
}

// round 15
// speedup vs baseline: 1.0756x; 1.0687x over previous
#include <cuda_runtime.h>
#include <math.h>
#include <stdint.h>

#define BB 4
#define CC 64
#define C3 192
#define TT 10
#define HH 64
#define WW 64
#define HW 4096
#define THW 40960
#define HEADS 4
#define CPH 16
#define NN 160
#define DD 4096
#define BH (BB*HEADS)
#define KSPL 8
#define KCH (DD/KSPL)   // 512

// ---------------- scratch (device globals) ---------------------------------
__device__ float g_qkv0[(size_t)BB * C3 * THW];
__device__ float g_qkv1[(size_t)BB * C3 * THW];
__device__ float g_Spart[(size_t)KSPL * BH * NN * NN];
__device__ float g_S[(size_t)BH * NN * NN];
__device__ float g_invq[BH * NN];
__device__ float g_invk[BH * NN];
__device__ float g_O[(size_t)BB * CC * THW];

// ---------------- packed f32x2 helpers --------------------------------------
__device__ __forceinline__ void ffma2(unsigned long long& d,
                                      unsigned long long a, unsigned long long b) {
    asm("fma.rn.f32x2 %0, %1, %2, %0;" : "+l"(d) : "l"(a), "l"(b));
}
__device__ __forceinline__ unsigned long long dup2(float x) {
    unsigned long long r;
    asm("mov.b64 %0, {%1, %1};" : "=l"(r) : "f"(x));
    return r;
}
__device__ __forceinline__ float2 unpk(unsigned long long v) {
    float2 r;
    asm("mov.b64 {%0, %1}, %2;" : "=f"(r.x), "=f"(r.y) : "l"(v));
    return r;
}
__device__ __forceinline__ unsigned long long lds64(const float* p) {
    return *(const unsigned long long*)p;
}
__device__ __forceinline__ uint32_t smem_u32(const void* p) {
    uint32_t a;
    asm("{ .reg .u64 t; cvta.to.shared.u64 t, %1; cvt.u32.u64 %0, t; }" : "=r"(a) : "l"(p));
    return a;
}
__device__ __forceinline__ void cpasync16(uint32_t dst, const void* src) {
    asm volatile("cp.async.cg.shared.global [%0], [%1], 16;" :: "r"(dst), "l"(src));
}
#define CP_COMMIT() asm volatile("cp.async.commit_group;" ::: "memory")
#define CP_WAIT1()  asm volatile("cp.async.wait_group 1;" ::: "memory")
#define CP_WAIT0()  asm volatile("cp.async.wait_group 0;" ::: "memory")

// ---------------- K1 / K7: projection GEMM (FFMA2, multi-CTA/SM) ------------
__global__ __launch_bounds__(128) void gemm_proj2(
    const float* __restrict__ W, const float* __restrict__ X, float* __restrict__ Y,
    long xbstride, long ybstride)
{
    __shared__ __align__(16) float As2[32][132];
    __shared__ __align__(16) float Bs[32][132];
    const int b  = blockIdx.z;
    const int m0 = blockIdx.y * 64;
    const int p0 = blockIdx.x * 128;
    const float* Xb = X + (size_t)b * xbstride;
    float*       Yb = Y + (size_t)b * ybstride;
    const int tid = threadIdx.x;
    const int tm = tid >> 4, tn = tid & 15;

    unsigned long long acc[8][4];
    #pragma unroll
    for (int i = 0; i < 8; i++)
        #pragma unroll
        for (int j = 0; j < 4; j++) acc[i][j] = 0ull;

    for (int kb = 0; kb < 64; kb += 32) {
        #pragma unroll
        for (int j = 0; j < 4; j++) {
            int idx = tid + j * 128;
            int row = idx >> 3;
            int kc  = (idx & 7) * 4;
            float4 w4 = *(const float4*)&W[(size_t)(m0 + row) * 64 + kb + kc];
            *(unsigned long long*)&As2[kc + 0][2 * row] = dup2(w4.x);
            *(unsigned long long*)&As2[kc + 1][2 * row] = dup2(w4.y);
            *(unsigned long long*)&As2[kc + 2][2 * row] = dup2(w4.z);
            *(unsigned long long*)&As2[kc + 3][2 * row] = dup2(w4.w);
        }
        #pragma unroll
        for (int j = 0; j < 8; j++) {
            int idx = tid + j * 128;
            int row = idx >> 5;
            int col = (idx & 31) * 4;
            *(float4*)&Bs[row][col] = *(const float4*)&Xb[(size_t)(kb + row) * THW + p0 + col];
        }
        __syncthreads();
        #pragma unroll 4
        for (int k = 0; k < 32; k++) {
            unsigned long long a[8], bp[4];
            #pragma unroll
            for (int mi = 0; mi < 8; mi++) a[mi] = lds64(&As2[k][2 * (tm * 8 + mi)]);
            #pragma unroll
            for (int u = 0; u < 4; u++)    bp[u] = lds64(&Bs[k][2 * tn + 32 * u]);
            #pragma unroll
            for (int mi = 0; mi < 8; mi++)
                #pragma unroll
                for (int u = 0; u < 4; u++) ffma2(acc[mi][u], a[mi], bp[u]);
        }
        __syncthreads();
    }
    #pragma unroll
    for (int mi = 0; mi < 8; mi++) {
        size_t base = (size_t)(m0 + tm * 8 + mi) * THW + p0 + 2 * tn;
        #pragma unroll
        for (int u = 0; u < 4; u++)
            *(float2*)&Yb[base + 32 * u] = unpk(acc[mi][u]);
    }
}

// ---------------- K2: depthwise 3x3 + temporal mix, 16x64 strips -------------
// Divide-free halo load: interior block shift/mask indexed; edge cols are
// always zero (full-width strip); boundary rows conditional on strip position.
__global__ __launch_bounds__(256) void dwconv_tmix4(
    const float* __restrict__ wdw, const float* __restrict__ wt,
    const float* __restrict__ bt, int c0, int cn)
{
    __shared__ __align__(16) float tile[TT][18][68];
    __shared__ float wts[TT * TT + TT];
    const int by = blockIdx.y;
    const int b  = by / cn;
    const int c  = c0 + by % cn;
    const int bc = b * C3 + c;
    const int h0 = blockIdx.x * 16;
    const float* src = g_qkv0 + (size_t)bc * THW;
    float*       dst = g_qkv1 + (size_t)bc * THW;
    const int tid = threadIdx.x;

    if (tid < TT * TT + TT)
        wts[tid] = (tid < TT * TT) ? wt[tid] : bt[tid - TT * TT];

    const bool top_ok = (h0 > 0);
    const bool bot_ok = (h0 + 16 < HH);
    #pragma unroll
    for (int t = 0; t < TT; t++) {
        const float* srcT = src + (size_t)t * HW;
        // interior 16x64: tile rows 1..16, cols 1..64 — always in bounds
        #pragma unroll
        for (int j = 0; j < 4; j++) {
            int idx = tid + j * 256;
            int yy = idx >> 6, xx = idx & 63;
            tile[t][yy + 1][xx + 1] = srcT[(h0 + yy) * WW + xx];
        }
        // boundary rows 0 / 17 (cols 0..65) + edge cols (always zero)
        if (tid < 132) {
            int isbot = tid >= 66;
            int x = tid - isbot * 66;       // 0..65
            int y = isbot ? 17 : 0;
            float v = 0.f;
            if (x >= 1 && x <= 64 && (isbot ? bot_ok : top_ok))
                v = srcT[(isbot ? (h0 + 16) : (h0 - 1)) * WW + x - 1];
            tile[t][y][x] = v;
        } else if (tid < 164) {
            int id2 = tid - 132;            // 0..31
            tile[t][1 + (id2 >> 1)][(id2 & 1) * 65] = 0.f;
        }
    }
    __syncthreads();

    float wd[9];
    #pragma unroll
    for (int i = 0; i < 9; i++) wd[i] = wdw[c * 9 + i];

    const int y  = tid >> 4;
    const int x0 = (tid & 15) * 4;

    float cv[4][TT];
    #pragma unroll
    for (int xx = 0; xx < 4; xx++)
        #pragma unroll
        for (int t = 0; t < TT; t++) cv[xx][t] = 0.f;

    #pragma unroll
    for (int t = 0; t < TT; t++) {
        #pragma unroll
        for (int kh = 0; kh < 3; kh++) {
            const float* row = &tile[t][y + kh][x0];
            float4 q = *(const float4*)row;
            float2 r2 = *(const float2*)(row + 4);
            float w0 = wd[kh * 3], w1 = wd[kh * 3 + 1], w2 = wd[kh * 3 + 2];
            cv[0][t] += w0 * q.x + w1 * q.y  + w2 * q.z;
            cv[1][t] += w0 * q.y + w1 * q.z  + w2 * q.w;
            cv[2][t] += w0 * q.z + w1 * q.w  + w2 * r2.x;
            cv[3][t] += w0 * q.w + w1 * r2.x + w2 * r2.y;
        }
    }

    const int hw = (h0 + y) * WW + x0;
    #pragma unroll
    for (int s = 0; s < TT; s++) {
        float bs = wts[TT * TT + s];
        float4 o = make_float4(bs, bs, bs, bs);
        #pragma unroll
        for (int t = 0; t < TT; t++) {
            float w = wts[s * TT + t];
            o.x += w * cv[0][t];
            o.y += w * cv[1][t];
            o.z += w * cv[2][t];
            o.w += w * cv[3][t];
        }
        *(float4*)&dst[(size_t)s * HW + hw] = o;
    }
}

// ---------------- K3a: L2 norms of q/k rows ---------------------------------
__global__ __launch_bounds__(256) void norms_kernel()
{
    const int warp = (blockIdx.x * 256 + threadIdx.x) >> 5;
    const int lane = threadIdx.x & 31;
    if (warp >= 2 * BH * NN) return;
    const int qk = warp / (BH * NN);
    const int r  = warp % (BH * NN);
    const int bh = r / NN, i = r % NN;
    const int b = bh / HEADS, h = bh % HEADS;
    const float* row = g_qkv1 + ((size_t)b * C3 + qk * CC + h * CPH) * THW + (size_t)i * DD;
    float s = 0.f;
    for (int d = lane * 4; d < DD; d += 128) {
        float4 v = *(const float4*)&row[d];
        s += v.x * v.x + v.y * v.y + v.z * v.z + v.w * v.w;
    }
    #pragma unroll
    for (int off = 16; off; off >>= 1) s += __shfl_xor_sync(0xffffffffu, s, off);
    if (lane == 0) {
        float inv = 1.f / fmaxf(sqrtf(s), 1e-12f);
        (qk ? g_invk : g_invq)[bh * NN + i] = inv;
    }
}

// ---------------- K3b: S partials = Q K^T -----------------------------------
#define QAS 330                        // dup-A row stride (floats)
#define QBS 166                        // K row stride (floats)
#define QK_STG (32 * QAS + 32 * QBS)   // one stage, floats

__global__ __launch_bounds__(512, 1) void qk_gemm7()
{
    extern __shared__ __align__(16) float sm[];
    const int bh = blockIdx.x;
    const int ks = blockIdx.y;
    const int b = bh >> 2, h = bh & 3;
    const float* Q  = g_qkv1 + ((size_t)b * C3 + h * CPH) * THW + (size_t)ks * KCH;
    const float* Kp = Q + (size_t)CC * THW;
    const int tid = threadIdx.x;
    const int tm = tid >> 4;
    const int tn = tid & 15;

    int lisK[5], lrow[5], lseg[5];
    #pragma unroll
    for (int j = 0; j < 5; j++) {
        int idx = tid + j * 512;
        lisK[j] = idx >= 1280;
        int l = idx - lisK[j] * 1280;
        lrow[j] = l >> 3;
        lseg[j] = (l & 7) * 4;
    }

    unsigned long long acc[5][5];
    #pragma unroll
    for (int i = 0; i < 5; i++)
        #pragma unroll
        for (int j = 0; j < 5; j++) acc[i][j] = 0ull;

    float4 r[5];
    auto gload = [&](int c) {
        const int kb = c * 32;
        #pragma unroll
        for (int j = 0; j < 5; j++)
            r[j] = *(const float4*)((lisK[j] ? Kp : Q) + (size_t)lrow[j] * DD + kb + lseg[j]);
    };
    auto sstore = [&](int s) {
        float* Qs2 = sm + s * QK_STG;
        float* Ksh = Qs2 + 32 * QAS;
        #pragma unroll
        for (int j = 0; j < 5; j++) {
            if (lisK[j]) {
                Ksh[(lseg[j] + 0) * QBS + lrow[j]] = r[j].x;
                Ksh[(lseg[j] + 1) * QBS + lrow[j]] = r[j].y;
                Ksh[(lseg[j] + 2) * QBS + lrow[j]] = r[j].z;
                Ksh[(lseg[j] + 3) * QBS + lrow[j]] = r[j].w;
            } else {
                *(unsigned long long*)&Qs2[(lseg[j] + 0) * QAS + 2 * lrow[j]] = dup2(r[j].x);
                *(unsigned long long*)&Qs2[(lseg[j] + 1) * QAS + 2 * lrow[j]] = dup2(r[j].y);
                *(unsigned long long*)&Qs2[(lseg[j] + 2) * QAS + 2 * lrow[j]] = dup2(r[j].z);
                *(unsigned long long*)&Qs2[(lseg[j] + 3) * QAS + 2 * lrow[j]] = dup2(r[j].w);
            }
        }
    };

    gload(0);
    sstore(0);
    __syncthreads();

    for (int c = 0; c < 16; c++) {
        if (c < 15) gload(c + 1);
        const float* Qs2 = sm + (c & 1) * QK_STG;
        const float* Ksh = Qs2 + 32 * QAS;
        #pragma unroll 4
        for (int k = 0; k < 32; k++) {
            unsigned long long a[5], bp[5];
            #pragma unroll
            for (int g = 0; g < 5; g++) a[g]  = lds64(&Qs2[k * QAS + 10 * tm + 2 * g]);
            #pragma unroll
            for (int u = 0; u < 5; u++) bp[u] = lds64(&Ksh[k * QBS + 2 * tn + 32 * u]);
            #pragma unroll
            for (int g = 0; g < 5; g++)
                #pragma unroll
                for (int u = 0; u < 5; u++) ffma2(acc[g][u], a[g], bp[u]);
        }
        if (c < 15) sstore((c + 1) & 1);
        __syncthreads();
    }

    float* Sp = g_Spart + ((size_t)ks * BH + bh) * NN * NN;
    #pragma unroll
    for (int g = 0; g < 5; g++) {
        int gi = tm * 5 + g;
        #pragma unroll
        for (int u = 0; u < 5; u++)
            *(float2*)&Sp[(size_t)gi * NN + 2 * tn + 32 * u] = unpk(acc[g][u]);
    }
}

// ---------------- K3c: reduce split-K + scale + softmax ---------------------
__global__ __launch_bounds__(256) void softmax2(const float* __restrict__ temp)
{
    const int warp = (blockIdx.x * 256 + threadIdx.x) >> 5;
    const int lane = threadIdx.x & 31;
    if (warp >= BH * NN) return;
    const int bh = warp / NN, i = warp % NN;
    const int h = bh & 3;
    const float scale_i = g_invq[bh * NN + i] * temp[h];
    float vals[5];
    float mx = -1e30f;
    #pragma unroll
    for (int j5 = 0; j5 < 5; j5++) {
        int j = lane + j5 * 32;
        float s = 0.f;
        #pragma unroll
        for (int ks = 0; ks < KSPL; ks++)
            s += g_Spart[(((size_t)ks * BH + bh) * NN + i) * NN + j];
        vals[j5] = s * scale_i * g_invk[bh * NN + j];
        mx = fmaxf(mx, vals[j5]);
    }
    #pragma unroll
    for (int off = 16; off; off >>= 1) mx = fmaxf(mx, __shfl_xor_sync(0xffffffffu, mx, off));
    float s = 0.f;
    #pragma unroll
    for (int j5 = 0; j5 < 5; j5++) { vals[j5] = __expf(vals[j5] - mx); s += vals[j5]; }
    #pragma unroll
    for (int off = 16; off; off >>= 1) s += __shfl_xor_sync(0xffffffffu, s, off);
    const float invs = 1.f / s;
    float* row = g_S + (size_t)bh * NN * NN + (size_t)i * NN;
    #pragma unroll
    for (int j5 = 0; j5 < 5; j5++) row[lane + j5 * 32] = vals[j5] * invs;
}

// ---------------- K3d: O = P V ----------------------------------------------
#define PS 36                          // P row stride (floats)
#define VS 264                         // V row stride (floats)
#define PV_STAGE (80 * PS + 32 * VS)   // floats

__global__ __launch_bounds__(256, 2) void pv_gemm5()
{
    extern __shared__ __align__(16) float sm[];
    const uint32_t sbase = smem_u32(sm);
    const int bh = blockIdx.z;
    const int b = bh >> 2, h = bh & 3;
    const int i0 = blockIdx.y * 80;
    const int d0 = blockIdx.x * 256;
    const float* P = g_S + (size_t)bh * NN * NN;
    const float* V = g_qkv1 + ((size_t)b * C3 + 2 * CC + h * CPH) * THW;
    float*       O = g_O   + ((size_t)b * CC + h * CPH) * THW;
    const int tid = threadIdx.x;
    const int tm = tid >> 4, tn = tid & 15;

    auto copy_chunk = [&](int c, int s) {
        const int kb = c * 32;
        #pragma unroll
        for (int j = 0; j < 3; j++) {
            int idx = tid + j * 256;
            if (idx < 640) {
                int row = idx >> 3, seg = idx & 7;
                cpasync16(sbase + (uint32_t)(s * PV_STAGE + row * PS + seg * 4) * 4u,
                          P + (size_t)(i0 + row) * NN + kb + seg * 4);
            }
        }
        #pragma unroll
        for (int j = 0; j < 8; j++) {
            int idx = tid + j * 256;
            int row = idx >> 6, col = (idx & 63) * 4;
            cpasync16(sbase + (uint32_t)(s * PV_STAGE + 80 * PS + row * VS + col) * 4u,
                      V + (size_t)(kb + row) * DD + d0 + col);
        }
        CP_COMMIT();
    };

    unsigned long long acc[5][8];
    #pragma unroll
    for (int i = 0; i < 5; i++)
        #pragma unroll
        for (int j = 0; j < 8; j++) acc[i][j] = 0ull;

    copy_chunk(0, 0);
    copy_chunk(1, 1);

    for (int c = 0; c < 5; c++) {
        if (c < 4) { CP_WAIT1(); } else { CP_WAIT0(); }
        __syncthreads();
        const float* Ps = sm + (c & 1) * PV_STAGE;
        const float* Vs = Ps + 80 * PS;
        #pragma unroll 4
        for (int k = 0; k < 32; k++) {
            unsigned long long bp[8];
            #pragma unroll
            for (int u = 0; u < 8; u++)
                bp[u] = lds64(&Vs[k * VS + 2 * tn + 32 * u]);
            #pragma unroll
            for (int v = 0; v < 5; v++) {
                unsigned long long a = dup2(Ps[(tm * 5 + v) * PS + k]);
                #pragma unroll
                for (int u = 0; u < 8; u++) ffma2(acc[v][u], a, bp[u]);
            }
        }
        __syncthreads();
        if (c < 3) copy_chunk(c + 2, c & 1);
    }

    #pragma unroll
    for (int v = 0; v < 5; v++) {
        size_t base = (size_t)(i0 + tm * 5 + v) * DD + d0 + 2 * tn;
        #pragma unroll
        for (int u = 0; u < 8; u++)
            *(float2*)&O[base + 32 * u] = unpk(acc[v][u]);
    }
}

// ---------------- host launcher --------------------------------------------
extern "C" void kernel_launch(void* const* d_in, const int* in_sizes, int n_in,
                              void* d_out, int out_size)
{
    const float* x      = (const float*)d_in[0];
    const float* w_qkv  = (const float*)d_in[1];
    const float* w_dw   = (const float*)d_in[2];
    const float* w_t    = (const float*)d_in[3];
    const float* b_t    = (const float*)d_in[4];
    const float* temp   = (const float*)d_in[5];
    const float* w_out  = (const float*)d_in[6];
    float* out = (float*)d_out;

    float *qkv0, *obuf;
    cudaGetSymbolAddress((void**)&qkv0, g_qkv0);
    cudaGetSymbolAddress((void**)&obuf, g_O);

    const int qk_smem = 2 * QK_STG * 4;     // 126976 B
    const int pv_smem = 2 * PV_STAGE * 4;   // 90624 B
    cudaFuncSetAttribute(qk_gemm7, cudaFuncAttributeMaxDynamicSharedMemorySize, qk_smem);
    cudaFuncSetAttribute(pv_gemm5, cudaFuncAttributeMaxDynamicSharedMemorySize, pv_smem);

    cudaStream_t s2;
    cudaEvent_t e1, e2;
    cudaStreamCreateWithFlags(&s2, cudaStreamNonBlocking);
    cudaEventCreateWithFlags(&e1, cudaEventDisableTiming);
    cudaEventCreateWithFlags(&e2, cudaEventDisableTiming);

    // K1: qkv projection (192 x 40960 per batch)
    gemm_proj2<<<dim3(THW / 128, C3 / 64, BB), 128>>>(
        w_qkv, x, qkv0, (long)CC * THW, (long)C3 * THW);

    // K2a: depthwise + temporal mix for q,k channels (critical path)
    dwconv_tmix4<<<dim3(4, BB * 128), 256>>>(w_dw, w_t, b_t, 0, 128);
    cudaEventRecord(e1, 0);

    // side stream: v channels + norms, overlapped with qk
    cudaStreamWaitEvent(s2, e1, 0);
    dwconv_tmix4<<<dim3(4, BB * 64), 256, 0, s2>>>(w_dw, w_t, b_t, 128, 64);
    norms_kernel<<<640, 256, 0, s2>>>();
    cudaEventRecord(e2, s2);

    // K3b: split-K scores (needs only q,k)
    qk_gemm7<<<dim3(BH, KSPL), 512, qk_smem>>>();

    // join: softmax needs norms; pv needs v
    cudaStreamWaitEvent(0, e2, 0);

    // K3c: reduce + scale + softmax
    softmax2<<<(BH * NN) / 8, 256>>>(temp);

    // K3d: O = P V
    pv_gemm5<<<dim3(DD / 256, NN / 80, BH), 256, pv_smem>>>();

    // K7: final projection -> d_out
    gemm_proj2<<<dim3(THW / 128, 1, BB), 128>>>(
        w_out, obuf, out, (long)CC * THW, (long)CC * THW);
}

// round 17
// speedup vs baseline: 1.1345x; 1.0548x over previous
#include <cuda_runtime.h>
#include <math.h>
#include <stdint.h>

#define BB 4
#define CC 64
#define C3 192
#define TT 10
#define HH 64
#define WW 64
#define HW 4096
#define THW 40960
#define HEADS 4
#define CPH 16
#define NN 160
#define DD 4096
#define BH (BB*HEADS)
#define KSPL 8
#define KCH (DD/KSPL)   // 512
#define NBH 8           // bh per lane (2 batches)

// ---------------- scratch (device globals) ---------------------------------
__device__ float g_qkv0[(size_t)BB * C3 * THW];
__device__ float g_qkv1[(size_t)BB * C3 * THW];
__device__ float g_Spart[(size_t)KSPL * BH * NN * NN];
__device__ float g_S[(size_t)BH * NN * NN];
__device__ float g_invq[BH * NN];
__device__ float g_invk[BH * NN];
__device__ float g_O[(size_t)BB * CC * THW];

// ---------------- packed f32x2 helpers --------------------------------------
__device__ __forceinline__ void ffma2(unsigned long long& d,
                                      unsigned long long a, unsigned long long b) {
    asm("fma.rn.f32x2 %0, %1, %2, %0;" : "+l"(d) : "l"(a), "l"(b));
}
__device__ __forceinline__ unsigned long long dup2(float x) {
    unsigned long long r;
    asm("mov.b64 %0, {%1, %1};" : "=l"(r) : "f"(x));
    return r;
}
__device__ __forceinline__ float2 unpk(unsigned long long v) {
    float2 r;
    asm("mov.b64 {%0, %1}, %2;" : "=f"(r.x), "=f"(r.y) : "l"(v));
    return r;
}
__device__ __forceinline__ unsigned long long lds64(const float* p) {
    return *(const unsigned long long*)p;
}
__device__ __forceinline__ uint32_t smem_u32(const void* p) {
    uint32_t a;
    asm("{ .reg .u64 t; cvta.to.shared.u64 t, %1; cvt.u32.u64 %0, t; }" : "=r"(a) : "l"(p));
    return a;
}
__device__ __forceinline__ void cpasync16(uint32_t dst, const void* src) {
    asm volatile("cp.async.cg.shared.global [%0], [%1], 16;" :: "r"(dst), "l"(src));
}
#define CP_COMMIT() asm volatile("cp.async.commit_group;" ::: "memory")
#define CP_WAIT1()  asm volatile("cp.async.wait_group 1;" ::: "memory")
#define CP_WAIT0()  asm volatile("cp.async.wait_group 0;" ::: "memory")

// ---------------- K1 / K7: projection GEMM (FFMA2, multi-CTA/SM) ------------
__global__ __launch_bounds__(128) void gemm_proj2(
    const float* __restrict__ W, const float* __restrict__ X, float* __restrict__ Y,
    long xbstride, long ybstride)
{
    __shared__ __align__(16) float As2[32][132];
    __shared__ __align__(16) float Bs[32][132];
    const int b  = blockIdx.z;
    const int m0 = blockIdx.y * 64;
    const int p0 = blockIdx.x * 128;
    const float* Xb = X + (size_t)b * xbstride;
    float*       Yb = Y + (size_t)b * ybstride;
    const int tid = threadIdx.x;
    const int tm = tid >> 4, tn = tid & 15;

    unsigned long long acc[8][4];
    #pragma unroll
    for (int i = 0; i < 8; i++)
        #pragma unroll
        for (int j = 0; j < 4; j++) acc[i][j] = 0ull;

    for (int kb = 0; kb < 64; kb += 32) {
        #pragma unroll
        for (int j = 0; j < 4; j++) {
            int idx = tid + j * 128;
            int row = idx >> 3;
            int kc  = (idx & 7) * 4;
            float4 w4 = *(const float4*)&W[(size_t)(m0 + row) * 64 + kb + kc];
            *(unsigned long long*)&As2[kc + 0][2 * row] = dup2(w4.x);
            *(unsigned long long*)&As2[kc + 1][2 * row] = dup2(w4.y);
            *(unsigned long long*)&As2[kc + 2][2 * row] = dup2(w4.z);
            *(unsigned long long*)&As2[kc + 3][2 * row] = dup2(w4.w);
        }
        #pragma unroll
        for (int j = 0; j < 8; j++) {
            int idx = tid + j * 128;
            int row = idx >> 5;
            int col = (idx & 31) * 4;
            *(float4*)&Bs[row][col] = *(const float4*)&Xb[(size_t)(kb + row) * THW + p0 + col];
        }
        __syncthreads();
        #pragma unroll 4
        for (int k = 0; k < 32; k++) {
            unsigned long long a[8], bp[4];
            #pragma unroll
            for (int mi = 0; mi < 8; mi++) a[mi] = lds64(&As2[k][2 * (tm * 8 + mi)]);
            #pragma unroll
            for (int u = 0; u < 4; u++)    bp[u] = lds64(&Bs[k][2 * tn + 32 * u]);
            #pragma unroll
            for (int mi = 0; mi < 8; mi++)
                #pragma unroll
                for (int u = 0; u < 4; u++) ffma2(acc[mi][u], a[mi], bp[u]);
        }
        __syncthreads();
    }
    #pragma unroll
    for (int mi = 0; mi < 8; mi++) {
        size_t base = (size_t)(m0 + tm * 8 + mi) * THW + p0 + 2 * tn;
        #pragma unroll
        for (int u = 0; u < 4; u++)
            *(float2*)&Yb[base + 32 * u] = unpk(acc[mi][u]);
    }
}

// ---------------- K2: depthwise 3x3 + temporal mix, 16x64 strips -------------
// batches [b0, b0+2); all 192 channels. grid (4 strips, 2*C3)
__global__ __launch_bounds__(256) void dwconv_tmix4(
    const float* __restrict__ wdw, const float* __restrict__ wt,
    const float* __restrict__ bt, int b0)
{
    __shared__ __align__(16) float tile[TT][18][68];
    __shared__ float wts[TT * TT + TT];
    const int by = blockIdx.y;
    const int b  = b0 + (by >= C3);
    const int c  = by - (by >= C3) * C3;
    const int bc = b * C3 + c;
    const int h0 = blockIdx.x * 16;
    const float* src = g_qkv0 + (size_t)bc * THW;
    float*       dst = g_qkv1 + (size_t)bc * THW;
    const int tid = threadIdx.x;

    if (tid < TT * TT + TT)
        wts[tid] = (tid < TT * TT) ? wt[tid] : bt[tid - TT * TT];

    const bool top_ok = (h0 > 0);
    const bool bot_ok = (h0 + 16 < HH);
    #pragma unroll
    for (int t = 0; t < TT; t++) {
        const float* srcT = src + (size_t)t * HW;
        #pragma unroll
        for (int j = 0; j < 4; j++) {
            int idx = tid + j * 256;
            int yy = idx >> 6, xx = idx & 63;
            tile[t][yy + 1][xx + 1] = srcT[(h0 + yy) * WW + xx];
        }
        if (tid < 132) {
            int isbot = tid >= 66;
            int x = tid - isbot * 66;
            int y = isbot ? 17 : 0;
            float v = 0.f;
            if (x >= 1 && x <= 64 && (isbot ? bot_ok : top_ok))
                v = srcT[(isbot ? (h0 + 16) : (h0 - 1)) * WW + x - 1];
            tile[t][y][x] = v;
        } else if (tid < 164) {
            int id2 = tid - 132;
            tile[t][1 + (id2 >> 1)][(id2 & 1) * 65] = 0.f;
        }
    }
    __syncthreads();

    float wd[9];
    #pragma unroll
    for (int i = 0; i < 9; i++) wd[i] = wdw[c * 9 + i];

    const int y  = tid >> 4;
    const int x0 = (tid & 15) * 4;

    float cv[4][TT];
    #pragma unroll
    for (int xx = 0; xx < 4; xx++)
        #pragma unroll
        for (int t = 0; t < TT; t++) cv[xx][t] = 0.f;

    #pragma unroll
    for (int t = 0; t < TT; t++) {
        #pragma unroll
        for (int kh = 0; kh < 3; kh++) {
            const float* row = &tile[t][y + kh][x0];
            float4 q = *(const float4*)row;
            float2 r2 = *(const float2*)(row + 4);
            float w0 = wd[kh * 3], w1 = wd[kh * 3 + 1], w2 = wd[kh * 3 + 2];
            cv[0][t] += w0 * q.x + w1 * q.y  + w2 * q.z;
            cv[1][t] += w0 * q.y + w1 * q.z  + w2 * q.w;
            cv[2][t] += w0 * q.z + w1 * q.w  + w2 * r2.x;
            cv[3][t] += w0 * q.w + w1 * r2.x + w2 * r2.y;
        }
    }

    const int hw = (h0 + y) * WW + x0;
    #pragma unroll
    for (int s = 0; s < TT; s++) {
        float bs = wts[TT * TT + s];
        float4 o = make_float4(bs, bs, bs, bs);
        #pragma unroll
        for (int t = 0; t < TT; t++) {
            float w = wts[s * TT + t];
            o.x += w * cv[0][t];
            o.y += w * cv[1][t];
            o.z += w * cv[2][t];
            o.w += w * cv[3][t];
        }
        *(float4*)&dst[(size_t)s * HW + hw] = o;
    }
}

// ---------------- K3a: L2 norms of q/k rows (bh range) ----------------------
__global__ __launch_bounds__(256) void norms_kernel(int bh0)
{
    const int warp = (blockIdx.x * 256 + threadIdx.x) >> 5;
    const int lane = threadIdx.x & 31;
    if (warp >= 2 * NBH * NN) return;
    const int qk = warp / (NBH * NN);
    const int r  = warp % (NBH * NN);
    const int bh = bh0 + r / NN, i = r % NN;
    const int b = bh / HEADS, h = bh % HEADS;
    const float* row = g_qkv1 + ((size_t)b * C3 + qk * CC + h * CPH) * THW + (size_t)i * DD;
    float s = 0.f;
    for (int d = lane * 4; d < DD; d += 128) {
        float4 v = *(const float4*)&row[d];
        s += v.x * v.x + v.y * v.y + v.z * v.z + v.w * v.w;
    }
    #pragma unroll
    for (int off = 16; off; off >>= 1) s += __shfl_xor_sync(0xffffffffu, s, off);
    if (lane == 0) {
        float inv = 1.f / fmaxf(sqrtf(s), 1e-12f);
        (qk ? g_invk : g_invq)[bh * NN + i] = inv;
    }
}

// ---------------- K3b: S partials = Q K^T -----------------------------------
#define QAS 330
#define QBS 166
#define QK_STG (32 * QAS + 32 * QBS)

__global__ __launch_bounds__(512, 1) void qk_gemm7(int bh0)
{
    extern __shared__ __align__(16) float sm[];
    const int bh = bh0 + blockIdx.x;
    const int ks = blockIdx.y;
    const int b = bh >> 2, h = bh & 3;
    const float* Q  = g_qkv1 + ((size_t)b * C3 + h * CPH) * THW + (size_t)ks * KCH;
    const float* Kp = Q + (size_t)CC * THW;
    const int tid = threadIdx.x;
    const int tm = tid >> 4;
    const int tn = tid & 15;

    int lisK[5], lrow[5], lseg[5];
    #pragma unroll
    for (int j = 0; j < 5; j++) {
        int idx = tid + j * 512;
        lisK[j] = idx >= 1280;
        int l = idx - lisK[j] * 1280;
        lrow[j] = l >> 3;
        lseg[j] = (l & 7) * 4;
    }

    unsigned long long acc[5][5];
    #pragma unroll
    for (int i = 0; i < 5; i++)
        #pragma unroll
        for (int j = 0; j < 5; j++) acc[i][j] = 0ull;

    float4 r[5];
    auto gload = [&](int c) {
        const int kb = c * 32;
        #pragma unroll
        for (int j = 0; j < 5; j++)
            r[j] = *(const float4*)((lisK[j] ? Kp : Q) + (size_t)lrow[j] * DD + kb + lseg[j]);
    };
    auto sstore = [&](int s) {
        float* Qs2 = sm + s * QK_STG;
        float* Ksh = Qs2 + 32 * QAS;
        #pragma unroll
        for (int j = 0; j < 5; j++) {
            if (lisK[j]) {
                Ksh[(lseg[j] + 0) * QBS + lrow[j]] = r[j].x;
                Ksh[(lseg[j] + 1) * QBS + lrow[j]] = r[j].y;
                Ksh[(lseg[j] + 2) * QBS + lrow[j]] = r[j].z;
                Ksh[(lseg[j] + 3) * QBS + lrow[j]] = r[j].w;
            } else {
                *(unsigned long long*)&Qs2[(lseg[j] + 0) * QAS + 2 * lrow[j]] = dup2(r[j].x);
                *(unsigned long long*)&Qs2[(lseg[j] + 1) * QAS + 2 * lrow[j]] = dup2(r[j].y);
                *(unsigned long long*)&Qs2[(lseg[j] + 2) * QAS + 2 * lrow[j]] = dup2(r[j].z);
                *(unsigned long long*)&Qs2[(lseg[j] + 3) * QAS + 2 * lrow[j]] = dup2(r[j].w);
            }
        }
    };

    gload(0);
    sstore(0);
    __syncthreads();

    for (int c = 0; c < 16; c++) {
        if (c < 15) gload(c + 1);
        const float* Qs2 = sm + (c & 1) * QK_STG;
        const float* Ksh = Qs2 + 32 * QAS;
        #pragma unroll 4
        for (int k = 0; k < 32; k++) {
            unsigned long long a[5], bp[5];
            #pragma unroll
            for (int g = 0; g < 5; g++) a[g]  = lds64(&Qs2[k * QAS + 10 * tm + 2 * g]);
            #pragma unroll
            for (int u = 0; u < 5; u++) bp[u] = lds64(&Ksh[k * QBS + 2 * tn + 32 * u]);
            #pragma unroll
            for (int g = 0; g < 5; g++)
                #pragma unroll
                for (int u = 0; u < 5; u++) ffma2(acc[g][u], a[g], bp[u]);
        }
        if (c < 15) sstore((c + 1) & 1);
        __syncthreads();
    }

    float* Sp = g_Spart + ((size_t)ks * BH + bh) * NN * NN;
    #pragma unroll
    for (int g = 0; g < 5; g++) {
        int gi = tm * 5 + g;
        #pragma unroll
        for (int u = 0; u < 5; u++)
            *(float2*)&Sp[(size_t)gi * NN + 2 * tn + 32 * u] = unpk(acc[g][u]);
    }
}

// ---------------- K3c: reduce split-K + scale + softmax ---------------------
__global__ __launch_bounds__(256) void softmax2(const float* __restrict__ temp, int bh0)
{
    const int warp = (blockIdx.x * 256 + threadIdx.x) >> 5;
    const int lane = threadIdx.x & 31;
    if (warp >= NBH * NN) return;
    const int bh = bh0 + warp / NN, i = warp % NN;
    const int h = bh & 3;
    const float scale_i = g_invq[bh * NN + i] * temp[h];
    float vals[5];
    float mx = -1e30f;
    #pragma unroll
    for (int j5 = 0; j5 < 5; j5++) {
        int j = lane + j5 * 32;
        float s = 0.f;
        #pragma unroll
        for (int ks = 0; ks < KSPL; ks++)
            s += g_Spart[(((size_t)ks * BH + bh) * NN + i) * NN + j];
        vals[j5] = s * scale_i * g_invk[bh * NN + j];
        mx = fmaxf(mx, vals[j5]);
    }
    #pragma unroll
    for (int off = 16; off; off >>= 1) mx = fmaxf(mx, __shfl_xor_sync(0xffffffffu, mx, off));
    float s = 0.f;
    #pragma unroll
    for (int j5 = 0; j5 < 5; j5++) { vals[j5] = __expf(vals[j5] - mx); s += vals[j5]; }
    #pragma unroll
    for (int off = 16; off; off >>= 1) s += __shfl_xor_sync(0xffffffffu, s, off);
    const float invs = 1.f / s;
    float* row = g_S + (size_t)bh * NN * NN + (size_t)i * NN;
    #pragma unroll
    for (int j5 = 0; j5 < 5; j5++) row[lane + j5 * 32] = vals[j5] * invs;
}

// ---------------- K3d: O = P V ----------------------------------------------
#define PS 36
#define VS 264
#define PV_STAGE (80 * PS + 32 * VS)

__global__ __launch_bounds__(256, 2) void pv_gemm5(int bh0)
{
    extern __shared__ __align__(16) float sm[];
    const uint32_t sbase = smem_u32(sm);
    const int bh = bh0 + blockIdx.z;
    const int b = bh >> 2, h = bh & 3;
    const int i0 = blockIdx.y * 80;
    const int d0 = blockIdx.x * 256;
    const float* P = g_S + (size_t)bh * NN * NN;
    const float* V = g_qkv1 + ((size_t)b * C3 + 2 * CC + h * CPH) * THW;
    float*       O = g_O   + ((size_t)b * CC + h * CPH) * THW;
    const int tid = threadIdx.x;
    const int tm = tid >> 4, tn = tid & 15;

    auto copy_chunk = [&](int c, int s) {
        const int kb = c * 32;
        #pragma unroll
        for (int j = 0; j < 3; j++) {
            int idx = tid + j * 256;
            if (idx < 640) {
                int row = idx >> 3, seg = idx & 7;
                cpasync16(sbase + (uint32_t)(s * PV_STAGE + row * PS + seg * 4) * 4u,
                          P + (size_t)(i0 + row) * NN + kb + seg * 4);
            }
        }
        #pragma unroll
        for (int j = 0; j < 8; j++) {
            int idx = tid + j * 256;
            int row = idx >> 6, col = (idx & 63) * 4;
            cpasync16(sbase + (uint32_t)(s * PV_STAGE + 80 * PS + row * VS + col) * 4u,
                      V + (size_t)(kb + row) * DD + d0 + col);
        }
        CP_COMMIT();
    };

    unsigned long long acc[5][8];
    #pragma unroll
    for (int i = 0; i < 5; i++)
        #pragma unroll
        for (int j = 0; j < 8; j++) acc[i][j] = 0ull;

    copy_chunk(0, 0);
    copy_chunk(1, 1);

    for (int c = 0; c < 5; c++) {
        if (c < 4) { CP_WAIT1(); } else { CP_WAIT0(); }
        __syncthreads();
        const float* Ps = sm + (c & 1) * PV_STAGE;
        const float* Vs = Ps + 80 * PS;
        #pragma unroll 4
        for (int k = 0; k < 32; k++) {
            unsigned long long bp[8];
            #pragma unroll
            for (int u = 0; u < 8; u++)
                bp[u] = lds64(&Vs[k * VS + 2 * tn + 32 * u]);
            #pragma unroll
            for (int v = 0; v < 5; v++) {
                unsigned long long a = dup2(Ps[(tm * 5 + v) * PS + k]);
                #pragma unroll
                for (int u = 0; u < 8; u++) ffma2(acc[v][u], a, bp[u]);
            }
        }
        __syncthreads();
        if (c < 3) copy_chunk(c + 2, c & 1);
    }

    #pragma unroll
    for (int v = 0; v < 5; v++) {
        size_t base = (size_t)(i0 + tm * 5 + v) * DD + d0 + 2 * tn;
        #pragma unroll
        for (int u = 0; u < 8; u++)
            *(float2*)&O[base + 32 * u] = unpk(acc[v][u]);
    }
}

// ---------------- host launcher --------------------------------------------
extern "C" void kernel_launch(void* const* d_in, const int* in_sizes, int n_in,
                              void* d_out, int out_size)
{
    const float* x      = (const float*)d_in[0];
    const float* w_qkv  = (const float*)d_in[1];
    const float* w_dw   = (const float*)d_in[2];
    const float* w_t    = (const float*)d_in[3];
    const float* b_t    = (const float*)d_in[4];
    const float* temp   = (const float*)d_in[5];
    const float* w_out  = (const float*)d_in[6];
    float* out = (float*)d_out;

    float *qkv0, *obuf;
    cudaGetSymbolAddress((void**)&qkv0, g_qkv0);
    cudaGetSymbolAddress((void**)&obuf, g_O);

    const int qk_smem = 2 * QK_STG * 4;     // 126976 B
    const int pv_smem = 2 * PV_STAGE * 4;   // 90624 B
    cudaFuncSetAttribute(qk_gemm7, cudaFuncAttributeMaxDynamicSharedMemorySize, qk_smem);
    cudaFuncSetAttribute(pv_gemm5, cudaFuncAttributeMaxDynamicSharedMemorySize, pv_smem);

    // ONE extra stream (matches the resource footprint that passed teardown
    // checks in earlier rounds); lane A runs on the capture stream itself.
    cudaStream_t s2;
    cudaEvent_t eF, eB;
    cudaStreamCreateWithFlags(&s2, cudaStreamNonBlocking);
    cudaEventCreateWithFlags(&eF, cudaEventDisableTiming);
    cudaEventCreateWithFlags(&eB, cudaEventDisableTiming);

    // fork
    cudaEventRecord(eF, 0);
    cudaStreamWaitEvent(s2, eF, 0);

    struct { cudaStream_t s; int b0; } lanes[2] = { {(cudaStream_t)0, 0}, {s2, 2} };
    for (int L = 0; L < 2; L++) {
        cudaStream_t s = lanes[L].s;
        const int b0  = lanes[L].b0;
        const int bh0 = b0 * HEADS;

        // K1: qkv projection for 2 batches
        gemm_proj2<<<dim3(THW / 128, C3 / 64, 2), 128, 0, s>>>(
            w_qkv, x + (size_t)b0 * CC * THW, qkv0 + (size_t)b0 * C3 * THW,
            (long)CC * THW, (long)C3 * THW);

        // K2: depthwise + temporal mix (all 192 channels, 2 batches)
        dwconv_tmix4<<<dim3(4, 2 * C3), 256, 0, s>>>(w_dw, w_t, b_t, b0);

        // K3a: q/k row norms (8 bh)
        norms_kernel<<<(2 * NBH * NN) / 8, 256, 0, s>>>(bh0);

        // K3b: split-K scores (8 bh x 8 ks = 64 CTAs)
        qk_gemm7<<<dim3(NBH, KSPL), 512, qk_smem, s>>>(bh0);

        // K3c: reduce + scale + softmax
        softmax2<<<(NBH * NN) / 8, 256, 0, s>>>(temp, bh0);

        // K3d: O = P V (16 x 2 x 8 = 256 CTAs)
        pv_gemm5<<<dim3(DD / 256, NN / 80, NBH), 256, pv_smem, s>>>(bh0);

        // K7: final projection for 2 batches
        gemm_proj2<<<dim3(THW / 128, 1, 2), 128, 0, s>>>(
            w_out, obuf + (size_t)b0 * CC * THW, out + (size_t)b0 * CC * THW,
            (long)CC * THW, (long)CC * THW);
    }

    // join
    cudaEventRecord(eB, s2);
    cudaStreamWaitEvent(0, eB, 0);
}